// round 2
// baseline (speedup 1.0000x reference)
#include <cuda_runtime.h>
#include <cstdint>
#include <math.h>

// ---------------- problem constants ----------------
#define BB   4096
#define DD   256
#define HH   512
#define KK   10
#define HEADN 94
#define LL   4
#define SS   10
#define NOUT (DD * 30)          // 7680 pruned output cols (logits/means/scales)

// ---------------- scratch (device globals; no allocation allowed) ----------------
__device__ float g_A0[BB * 2 * DD];          // concat(x*mask, mask)   4096x512
__device__ float g_H[BB * HH];               // running hidden state
__device__ float g_T[BB * HH];               // temp
__device__ float g_WFP[HH * NOUT];           // gathered W_fin (512 x 7680)
__device__ float g_BFP[NOUT];                // gathered b_fin
__device__ float g_OUT30[(size_t)BB * NOUT]; // final params (4096 x 7680)

// ---------------- threefry2x32 (bit-exact JAX) ----------------
__host__ __device__ __forceinline__ uint32_t rotl32(uint32_t x, int r) {
#if defined(__CUDA_ARCH__)
    return __funnelshift_l(x, x, r);
#else
    return (x << r) | (x >> (32 - r));
#endif
}

__host__ __device__ __forceinline__ void threefry2x32(
    uint32_t k0, uint32_t k1, uint32_t x0, uint32_t x1,
    uint32_t& o0, uint32_t& o1)
{
    uint32_t k2 = k0 ^ k1 ^ 0x1BD11BDAu;
    x0 += k0; x1 += k1;
    // round group 1 (13,15,26,6)
    x0 += x1; x1 = rotl32(x1, 13); x1 ^= x0;
    x0 += x1; x1 = rotl32(x1, 15); x1 ^= x0;
    x0 += x1; x1 = rotl32(x1, 26); x1 ^= x0;
    x0 += x1; x1 = rotl32(x1, 6);  x1 ^= x0;
    x0 += k1; x1 += k2 + 1u;
    // group 2 (17,29,16,24)
    x0 += x1; x1 = rotl32(x1, 17); x1 ^= x0;
    x0 += x1; x1 = rotl32(x1, 29); x1 ^= x0;
    x0 += x1; x1 = rotl32(x1, 16); x1 ^= x0;
    x0 += x1; x1 = rotl32(x1, 24); x1 ^= x0;
    x0 += k2; x1 += k0 + 2u;
    // group 3 (13,15,26,6)
    x0 += x1; x1 = rotl32(x1, 13); x1 ^= x0;
    x0 += x1; x1 = rotl32(x1, 15); x1 ^= x0;
    x0 += x1; x1 = rotl32(x1, 26); x1 ^= x0;
    x0 += x1; x1 = rotl32(x1, 6);  x1 ^= x0;
    x0 += k0; x1 += k1 + 3u;
    // group 4 (17,29,16,24)
    x0 += x1; x1 = rotl32(x1, 17); x1 ^= x0;
    x0 += x1; x1 = rotl32(x1, 29); x1 ^= x0;
    x0 += x1; x1 = rotl32(x1, 16); x1 ^= x0;
    x0 += x1; x1 = rotl32(x1, 24); x1 ^= x0;
    x0 += k1; x1 += k2 + 4u;
    // group 5 (13,15,26,6)
    x0 += x1; x1 = rotl32(x1, 13); x1 ^= x0;
    x0 += x1; x1 = rotl32(x1, 15); x1 ^= x0;
    x0 += x1; x1 = rotl32(x1, 26); x1 ^= x0;
    x0 += x1; x1 = rotl32(x1, 6);  x1 ^= x0;
    x0 += k2; x1 += k0 + 5u;
    o0 = x0; o1 = x1;
}

// partitionable-mode 32-bit random bits: counter (0, i), output o0 ^ o1
__device__ __forceinline__ uint32_t tf_bits(uint32_t k0, uint32_t k1, uint32_t idx) {
    uint32_t o0, o1;
    threefry2x32(k0, k1, 0u, idx, o0, o1);
    return o0 ^ o1;
}

// ---------------- XLA-exact erfinv (Giles, f32 path) ----------------
__device__ __forceinline__ float erfinv_xla(float x) {
    float w = -logf((1.0f - x) * (1.0f + x));
    float p;
    if (w < 5.0f) {
        w -= 2.5f;
        p = 2.81022636e-08f;
        p = fmaf(p, w, 3.43273939e-07f);
        p = fmaf(p, w, -3.5233877e-06f);
        p = fmaf(p, w, -4.39150654e-06f);
        p = fmaf(p, w, 0.00021858087f);
        p = fmaf(p, w, -0.00125372503f);
        p = fmaf(p, w, -0.00417768164f);
        p = fmaf(p, w, 0.246640727f);
        p = fmaf(p, w, 1.50140941f);
    } else {
        w = sqrtf(w) - 3.0f;
        p = -0.000200214257f;
        p = fmaf(p, w, 0.000100950558f);
        p = fmaf(p, w, 0.00134934322f);
        p = fmaf(p, w, -0.00367342844f);
        p = fmaf(p, w, 0.00573950773f);
        p = fmaf(p, w, -0.0076224613f);
        p = fmaf(p, w, 0.00943887047f);
        p = fmaf(p, w, 1.00167406f);
        p = fmaf(p, w, 2.83297682f);
    }
    return p * x;
}

__device__ __forceinline__ float bits_to_unit(uint32_t b) {
    return __uint_as_float((b >> 9) | 0x3F800000u) - 1.0f;
}

__device__ __forceinline__ float gumbel_from_bits(uint32_t bits) {
    const float TINY = 1.17549435e-38f;
    float f = bits_to_unit(bits);
    float u = fmaxf(TINY, f + TINY);   // (1 - tiny) rounds to 1.0f in f32
    return -logf(-logf(u));
}

// ---------------- small prep kernels ----------------
__global__ void prep_kernel(const float* __restrict__ x, const float* __restrict__ mask) {
    int t = blockIdx.x * blockDim.x + threadIdx.x;
    if (t >= BB * 2 * DD) return;
    int b = t >> 9;
    int c = t & 511;
    float v;
    if (c < DD) v = x[b * DD + c] * mask[b * DD + c];
    else        v = mask[b * DD + (c - DD)];
    g_A0[t] = v;
}

__global__ void gather_kernel(const float* __restrict__ Wf, const float* __restrict__ bf) {
    int t = blockIdx.x * blockDim.x + threadIdx.x;
    const int total = HH * NOUT;
    if (t < total) {
        int c = t % NOUT;
        int h = t / NOUT;
        int d = c / 30, j = c - d * 30;
        g_WFP[t] = Wf[(size_t)h * (DD * HEADN) + d * HEADN + j];
    } else if (t < total + NOUT) {
        int c = t - total;
        int d = c / 30, j = c - d * 30;
        g_BFP[c] = bf[d * HEADN + j];
    }
}

// ---------------- fp32 SGEMM 128x128x8, 256 thr, 8x8 microtile ----------------
template <bool RELU_A, bool ADD_C>
__global__ __launch_bounds__(256, 2) void sgemm128(
    const float* __restrict__ A, const float* __restrict__ Bm,
    const float* __restrict__ bias, float* __restrict__ C,
    int M, int N, int Kd)
{
    __shared__ float As[8][136];   // transposed A tile, padded
    __shared__ float Bs[8][128];

    const int t  = threadIdx.x;
    const int bm = blockIdx.y * 128;
    const int bn = blockIdx.x * 128;
    const int tx = t & 15;
    const int ty = t >> 4;

    const int arow = t >> 1;         // 0..127
    const int akq  = (t & 1) * 4;    // 0 or 4
    const int brow = t >> 5;         // 0..7
    const int bcol = (t & 31) * 4;   // 0..124

    const float* Ap = A + (size_t)(bm + arow) * Kd + akq;
    const float* Bp = Bm + (size_t)brow * N + bn + bcol;

    float acc[8][8];
#pragma unroll
    for (int i = 0; i < 8; i++)
#pragma unroll
        for (int j = 0; j < 8; j++) acc[i][j] = 0.0f;

    for (int k0 = 0; k0 < Kd; k0 += 8) {
        float4 av = *reinterpret_cast<const float4*>(Ap + k0);
        if (RELU_A) {
            av.x = fmaxf(av.x, 0.f); av.y = fmaxf(av.y, 0.f);
            av.z = fmaxf(av.z, 0.f); av.w = fmaxf(av.w, 0.f);
        }
        float4 bv = *reinterpret_cast<const float4*>(Bp + (size_t)k0 * N);
        As[akq + 0][arow] = av.x;
        As[akq + 1][arow] = av.y;
        As[akq + 2][arow] = av.z;
        As[akq + 3][arow] = av.w;
        *reinterpret_cast<float4*>(&Bs[brow][bcol]) = bv;
        __syncthreads();
#pragma unroll
        for (int kk = 0; kk < 8; kk++) {
            float a[8], bb[8];
            *reinterpret_cast<float4*>(a)     = *reinterpret_cast<const float4*>(&As[kk][ty * 8]);
            *reinterpret_cast<float4*>(a + 4) = *reinterpret_cast<const float4*>(&As[kk][ty * 8 + 4]);
            *reinterpret_cast<float4*>(bb)     = *reinterpret_cast<const float4*>(&Bs[kk][tx * 8]);
            *reinterpret_cast<float4*>(bb + 4) = *reinterpret_cast<const float4*>(&Bs[kk][tx * 8 + 4]);
#pragma unroll
            for (int i = 0; i < 8; i++)
#pragma unroll
                for (int j = 0; j < 8; j++)
                    acc[i][j] = fmaf(a[i], bb[j], acc[i][j]);
        }
        __syncthreads();
    }

#pragma unroll
    for (int i = 0; i < 8; i++) {
        float* crow = C + (size_t)(bm + ty * 8 + i) * N + bn + tx * 8;
#pragma unroll
        for (int jj = 0; jj < 2; jj++) {
            int nn = bn + tx * 8 + jj * 4;
            float4 r;
            r.x = acc[i][jj * 4 + 0] + bias[nn + 0];
            r.y = acc[i][jj * 4 + 1] + bias[nn + 1];
            r.z = acc[i][jj * 4 + 2] + bias[nn + 2];
            r.w = acc[i][jj * 4 + 3] + bias[nn + 3];
            if (ADD_C) {
                float4 c0 = *reinterpret_cast<const float4*>(crow + jj * 4);
                r.x += c0.x; r.y += c0.y; r.z += c0.z; r.w += c0.w;
            }
            *reinterpret_cast<float4*>(crow + jj * 4) = r;
        }
    }
}

// ---------------- fused tail: ll, mean, sampling ----------------
__global__ void fused_tail(const float* __restrict__ x, const float* __restrict__ mask,
                           float* __restrict__ out,
                           uint32_t kc0, uint32_t kc1, uint32_t kn0, uint32_t kn1)
{
    int t = blockIdx.x * blockDim.x + threadIdx.x;
    if (t >= BB * DD) return;
    int b = t >> 8;
    int d = t & (DD - 1);

    const float* row = g_OUT30 + (size_t)b * NOUT + d * 30;
    float lg[KK], mu[KK], sc[KK];
#pragma unroll
    for (int j = 0; j < KK; j++) lg[j] = row[j];
#pragma unroll
    for (int j = 0; j < KK; j++) mu[j] = row[KK + j];
#pragma unroll
    for (int j = 0; j < KK; j++) {
        float v = row[2 * KK + j];
        // jax.nn.softplus = max(v,0) + log1p(exp(-|v|))
        sc[j] = fmaxf(v, 0.0f) + log1pf(expf(-fabsf(v))) + 0.001f;
    }
    float q  = 1.0f - mask[t];
    float xu = x[t] * q;

    // log_softmax pieces
    float mx = lg[0];
#pragma unroll
    for (int j = 1; j < KK; j++) mx = fmaxf(mx, lg[j]);
    float se = 0.0f;
#pragma unroll
    for (int j = 0; j < KK; j++) se += expf(lg[j] - mx);
    float lse = logf(se);

    // proposal_ll = logsumexp(log_w + comp_ll) * q
    float term[KK];
    float m2 = -1e30f;
#pragma unroll
    for (int j = 0; j < KK; j++) {
        float z   = (xu - mu[j]) / sc[j];
        float cll = -0.5f * z * z - logf(sc[j]) - 0.9189385332046727f;
        term[j] = (lg[j] - mx - lse) + cll;
        m2 = fmaxf(m2, term[j]);
    }
    float s2 = 0.0f;
#pragma unroll
    for (int j = 0; j < KK; j++) s2 += expf(term[j] - m2);
    out[t] = (m2 + logf(s2)) * q;

    // proposal_mean = sum(softmax * means) * q
    float pm = 0.0f;
#pragma unroll
    for (int j = 0; j < KK; j++) pm += (expf(lg[j] - mx) / se) * mu[j];
    out[BB * DD + SS * BB * DD + t] = pm * q;

    // ---- sampling: categorical (gumbel argmax) + normal ----
    // partitionable threefry: element i of (S,B,D,K) uses counter (0, i),
    // bits = o0 ^ o1.
    float* smp = out + BB * DD;

#pragma unroll 1
    for (int s = 0; s < SS; s++) {
        uint32_t idx_e = (uint32_t)(s * BB + b) * DD + (uint32_t)d;  // (S,B,D) flat
        uint32_t base  = idx_e * KK;                                  // (S,B,D,K) flat
        float best = -1e30f;
        int a = 0;
#pragma unroll
        for (int j = 0; j < KK; j++) {
            uint32_t bits = tf_bits(kc0, kc1, base + j);
            float v = lg[j] + gumbel_from_bits(bits);
            if (v > best) { best = v; a = j; }
        }
        // select means/scales with static indices (keep arrays in registers)
        float mua = 0.f, sca = 0.f;
#pragma unroll
        for (int j = 0; j < KK; j++) {
            if (a == j) { mua = mu[j]; sca = sc[j]; }
        }
        uint32_t ebits = tf_bits(kn0, kn1, idx_e);
        const float LO = -0.99999994f;
        float u = fmaxf(LO, fmaf(bits_to_unit(ebits), 2.0f, LO));
        float eps = 1.41421356237309515f * erfinv_xla(u);
        smp[(b * SS + s) * DD + d] = (mua + sca * eps) * q;
    }
}

// ---------------- launch ----------------
extern "C" void kernel_launch(void* const* d_in, const int* in_sizes, int n_in,
                              void* d_out, int out_size)
{
    const float* x     = (const float*)d_in[0];
    const float* mask  = (const float*)d_in[1];
    const float* W_in  = (const float*)d_in[2];
    const float* b_in  = (const float*)d_in[3];
    const float* W1    = (const float*)d_in[4];
    const float* b1    = (const float*)d_in[5];
    const float* W2    = (const float*)d_in[6];
    const float* b2    = (const float*)d_in[7];
    const float* W_fin = (const float*)d_in[8];
    const float* b_fin = (const float*)d_in[9];
    float* out = (float*)d_out;

    float *dA0, *dH, *dT, *dWFP, *dBFP, *dOUT30;
    cudaGetSymbolAddress((void**)&dA0,    g_A0);
    cudaGetSymbolAddress((void**)&dH,     g_H);
    cudaGetSymbolAddress((void**)&dT,     g_T);
    cudaGetSymbolAddress((void**)&dWFP,   g_WFP);
    cudaGetSymbolAddress((void**)&dBFP,   g_BFP);
    cudaGetSymbolAddress((void**)&dOUT30, g_OUT30);

    // JAX partitionable (fold-like) split of key(1234):
    //   child j = threefry((0,1234), (0, j)) -> [o0, o1]
    uint32_t kc0, kc1, kn0, kn1;
    threefry2x32(0u, 1234u, 0u, 0u, kc0, kc1);   // keys[0] -> categorical
    threefry2x32(0u, 1234u, 0u, 1u, kn0, kn1);   // keys[1] -> normal

    prep_kernel<<<(BB * 2 * DD + 255) / 256, 256>>>(x, mask);
    gather_kernel<<<(HH * NOUT + NOUT + 255) / 256, 256>>>(W_fin, b_fin);

    dim3 blk(256);
    dim3 g1(HH / 128, BB / 128);
    // h = a0 @ W_in + b_in
    sgemm128<false, false><<<g1, blk>>>(dA0, W_in, b_in, dH, BB, HH, 2 * DD);
    for (int l = 0; l < LL; l++) {
        // t = relu(h) @ W1[l] + b1[l]
        sgemm128<true, false><<<g1, blk>>>(dH, W1 + (size_t)l * HH * HH, b1 + l * HH, dT, BB, HH, HH);
        // h = h + relu(t) @ W2[l] + b2[l]
        sgemm128<true, true><<<g1, blk>>>(dT, W2 + (size_t)l * HH * HH, b2 + l * HH, dH, BB, HH, HH);
    }
    // out30 = h @ WFP + bFP   (pruned to the 30 used head columns)
    dim3 g2(NOUT / 128, BB / 128);
    sgemm128<false, false><<<g2, blk>>>(dH, dWFP, dBFP, dOUT30, BB, NOUT, HH);

    fused_tail<<<(BB * DD + 255) / 256, 256>>>(x, mask, out, kc0, kc1, kn0, kn1);
}

// round 3
// speedup vs baseline: 1.1529x; 1.1529x over previous
#include <cuda_runtime.h>
#include <cstdint>
#include <math.h>

// ---------------- problem constants ----------------
#define BB   4096
#define DD   256
#define HH   512
#define KK   10
#define HEADN 94
#define LL   4
#define SS   10
#define NOUT (DD * 30)          // 7680 pruned output cols (logits/means/scales)

typedef unsigned long long ull;

// ---------------- scratch (device globals; no allocation allowed) ----------------
__device__ float g_A0[BB * 2 * DD];          // concat(x*mask, mask)   4096x512
__device__ float g_H[BB * HH];               // running hidden state
__device__ float g_T[BB * HH];               // temp
__device__ float g_WFP[HH * NOUT];           // gathered W_fin (512 x 7680)
__device__ float g_BFP[NOUT];                // gathered b_fin
__device__ float g_OUT30[(size_t)BB * NOUT]; // final params (4096 x 7680)

// ---------------- f32x2 helpers ----------------
__device__ __forceinline__ ull pack2(float lo, float hi) {
    ull r; asm("mov.b64 %0, {%1, %2};" : "=l"(r) : "f"(lo), "f"(hi)); return r;
}
__device__ __forceinline__ ull fma2(ull a, ull b, ull c) {
    ull r; asm("fma.rn.f32x2 %0, %1, %2, %3;" : "=l"(r) : "l"(a), "l"(b), "l"(c)); return r;
}
__device__ __forceinline__ void unpack2(ull v, float& lo, float& hi) {
    asm("mov.b64 {%0, %1}, %2;" : "=f"(lo), "=f"(hi) : "l"(v));
}

// ---------------- threefry2x32 (bit-exact JAX) ----------------
__host__ __device__ __forceinline__ uint32_t rotl32(uint32_t x, int r) {
#if defined(__CUDA_ARCH__)
    return __funnelshift_l(x, x, r);
#else
    return (x << r) | (x >> (32 - r));
#endif
}

__host__ __device__ __forceinline__ void threefry2x32(
    uint32_t k0, uint32_t k1, uint32_t x0, uint32_t x1,
    uint32_t& o0, uint32_t& o1)
{
    uint32_t k2 = k0 ^ k1 ^ 0x1BD11BDAu;
    x0 += k0; x1 += k1;
    x0 += x1; x1 = rotl32(x1, 13); x1 ^= x0;
    x0 += x1; x1 = rotl32(x1, 15); x1 ^= x0;
    x0 += x1; x1 = rotl32(x1, 26); x1 ^= x0;
    x0 += x1; x1 = rotl32(x1, 6);  x1 ^= x0;
    x0 += k1; x1 += k2 + 1u;
    x0 += x1; x1 = rotl32(x1, 17); x1 ^= x0;
    x0 += x1; x1 = rotl32(x1, 29); x1 ^= x0;
    x0 += x1; x1 = rotl32(x1, 16); x1 ^= x0;
    x0 += x1; x1 = rotl32(x1, 24); x1 ^= x0;
    x0 += k2; x1 += k0 + 2u;
    x0 += x1; x1 = rotl32(x1, 13); x1 ^= x0;
    x0 += x1; x1 = rotl32(x1, 15); x1 ^= x0;
    x0 += x1; x1 = rotl32(x1, 26); x1 ^= x0;
    x0 += x1; x1 = rotl32(x1, 6);  x1 ^= x0;
    x0 += k0; x1 += k1 + 3u;
    x0 += x1; x1 = rotl32(x1, 17); x1 ^= x0;
    x0 += x1; x1 = rotl32(x1, 29); x1 ^= x0;
    x0 += x1; x1 = rotl32(x1, 16); x1 ^= x0;
    x0 += x1; x1 = rotl32(x1, 24); x1 ^= x0;
    x0 += k1; x1 += k2 + 4u;
    x0 += x1; x1 = rotl32(x1, 13); x1 ^= x0;
    x0 += x1; x1 = rotl32(x1, 15); x1 ^= x0;
    x0 += x1; x1 = rotl32(x1, 26); x1 ^= x0;
    x0 += x1; x1 = rotl32(x1, 6);  x1 ^= x0;
    x0 += k2; x1 += k0 + 5u;
    o0 = x0; o1 = x1;
}

// partitionable-mode 32-bit random bits: counter (0, i), output o0 ^ o1
__device__ __forceinline__ uint32_t tf_bits(uint32_t k0, uint32_t k1, uint32_t idx) {
    uint32_t o0, o1;
    threefry2x32(k0, k1, 0u, idx, o0, o1);
    return o0 ^ o1;
}

// ---------------- XLA-exact erfinv (Giles, f32 path) ----------------
__device__ __forceinline__ float erfinv_xla(float x) {
    float w = -logf((1.0f - x) * (1.0f + x));
    float p;
    if (w < 5.0f) {
        w -= 2.5f;
        p = 2.81022636e-08f;
        p = fmaf(p, w, 3.43273939e-07f);
        p = fmaf(p, w, -3.5233877e-06f);
        p = fmaf(p, w, -4.39150654e-06f);
        p = fmaf(p, w, 0.00021858087f);
        p = fmaf(p, w, -0.00125372503f);
        p = fmaf(p, w, -0.00417768164f);
        p = fmaf(p, w, 0.246640727f);
        p = fmaf(p, w, 1.50140941f);
    } else {
        w = sqrtf(w) - 3.0f;
        p = -0.000200214257f;
        p = fmaf(p, w, 0.000100950558f);
        p = fmaf(p, w, 0.00134934322f);
        p = fmaf(p, w, -0.00367342844f);
        p = fmaf(p, w, 0.00573950773f);
        p = fmaf(p, w, -0.0076224613f);
        p = fmaf(p, w, 0.00943887047f);
        p = fmaf(p, w, 1.00167406f);
        p = fmaf(p, w, 2.83297682f);
    }
    return p * x;
}

__device__ __forceinline__ float bits_to_unit(uint32_t b) {
    return __uint_as_float((b >> 9) | 0x3F800000u) - 1.0f;
}

__device__ __forceinline__ float gumbel_from_bits(uint32_t bits) {
    const float TINY = 1.17549435e-38f;
    float f = bits_to_unit(bits);
    float u = fmaxf(TINY, f + TINY);
    return -logf(-logf(u));
}

// ---------------- small prep kernels ----------------
__global__ void prep_kernel(const float* __restrict__ x, const float* __restrict__ mask) {
    int t = blockIdx.x * blockDim.x + threadIdx.x;
    if (t >= BB * 2 * DD) return;
    int b = t >> 9;
    int c = t & 511;
    float v;
    if (c < DD) v = x[b * DD + c] * mask[b * DD + c];
    else        v = mask[b * DD + (c - DD)];
    g_A0[t] = v;
}

__global__ void gather_kernel(const float* __restrict__ Wf, const float* __restrict__ bf) {
    int t = blockIdx.x * blockDim.x + threadIdx.x;
    const int total = HH * NOUT;
    if (t < total) {
        int c = t % NOUT;
        int h = t / NOUT;
        int d = c / 30, j = c - d * 30;
        g_WFP[t] = Wf[(size_t)h * (DD * HEADN) + d * HEADN + j];
    } else if (t < total + NOUT) {
        int c = t - total;
        int d = c / 30, j = c - d * 30;
        g_BFP[c] = bf[d * HEADN + j];
    }
}

// ---------------- fp32 SGEMM, f32x2 inner, double-buffered ----------------
// Tile: BM x 128, BK=8, NTHR = 2*BM threads, 8x8 microtile per thread.
template <int NTHR, bool RELU_A, bool ADD_C>
__global__ __launch_bounds__(NTHR, 2) void sgemm_f32x2(
    const float* __restrict__ A, const float* __restrict__ Bm,
    const float* __restrict__ bias, float* __restrict__ C,
    int M, int N, int Kd)
{
    constexpr int BM = NTHR / 2;
    __shared__ float As[2][8][136];   // transposed A tile, padded
    __shared__ float Bs[2][8][128];

    const int t  = threadIdx.x;
    const int bm = blockIdx.y * BM;
    const int bn = blockIdx.x * 128;
    const int tx = t & 15;
    const int ty = t >> 4;          // 0..NTHR/16-1  (rows of 8)

    // A fragment: 4 consecutive k per thread
    const int arow = t >> 1;        // 0..BM-1
    const int akq  = (t & 1) * 4;   // 0 or 4
    const float* Ap = A + (size_t)(bm + arow) * Kd + akq;

    // B fragment
    const int brow256 = t >> 5;           // NTHR==256: 0..7
    const int bcol256 = (t & 31) * 4;
    const int brow128 = t >> 4;           // NTHR==128: 0..7
    const int bcol128 = (t & 15) * 8;

    ull acc2[8][4];
#pragma unroll
    for (int i = 0; i < 8; i++)
#pragma unroll
        for (int j = 0; j < 4; j++) acc2[i][j] = 0ull;

    float4 aR, bR0, bR1;

    auto loadG = [&](int k0) {
        aR = *reinterpret_cast<const float4*>(Ap + k0);
        if (RELU_A) {
            aR.x = fmaxf(aR.x, 0.f); aR.y = fmaxf(aR.y, 0.f);
            aR.z = fmaxf(aR.z, 0.f); aR.w = fmaxf(aR.w, 0.f);
        }
        if (NTHR == 256) {
            bR0 = *reinterpret_cast<const float4*>(Bm + (size_t)(k0 + brow256) * N + bn + bcol256);
        } else {
            bR0 = *reinterpret_cast<const float4*>(Bm + (size_t)(k0 + brow128) * N + bn + bcol128);
            bR1 = *reinterpret_cast<const float4*>(Bm + (size_t)(k0 + brow128) * N + bn + bcol128 + 4);
        }
    };
    auto storeS = [&](int p) {
        As[p][akq + 0][arow] = aR.x;
        As[p][akq + 1][arow] = aR.y;
        As[p][akq + 2][arow] = aR.z;
        As[p][akq + 3][arow] = aR.w;
        if (NTHR == 256) {
            *reinterpret_cast<float4*>(&Bs[p][brow256][bcol256]) = bR0;
        } else {
            *reinterpret_cast<float4*>(&Bs[p][brow128][bcol128]) = bR0;
            *reinterpret_cast<float4*>(&Bs[p][brow128][bcol128 + 4]) = bR1;
        }
    };

    loadG(0);
    storeS(0);
    __syncthreads();

    const int T = Kd >> 3;
    int p = 0;
#pragma unroll 1
    for (int tk = 0; tk < T; tk++) {
        if (tk + 1 < T) loadG((tk + 1) << 3);
#pragma unroll
        for (int kk = 0; kk < 8; kk++) {
            float a[8];
            *reinterpret_cast<float4*>(a)     = *reinterpret_cast<const float4*>(&As[p][kk][ty * 8]);
            *reinterpret_cast<float4*>(a + 4) = *reinterpret_cast<const float4*>(&As[p][kk][ty * 8 + 4]);
            ulonglong2 bq0 = *reinterpret_cast<const ulonglong2*>(&Bs[p][kk][tx * 8]);
            ulonglong2 bq1 = *reinterpret_cast<const ulonglong2*>(&Bs[p][kk][tx * 8 + 4]);
#pragma unroll
            for (int i = 0; i < 8; i++) {
                ull a2 = pack2(a[i], a[i]);
                acc2[i][0] = fma2(a2, bq0.x, acc2[i][0]);
                acc2[i][1] = fma2(a2, bq0.y, acc2[i][1]);
                acc2[i][2] = fma2(a2, bq1.x, acc2[i][2]);
                acc2[i][3] = fma2(a2, bq1.y, acc2[i][3]);
            }
        }
        if (tk + 1 < T) {
            storeS(p ^ 1);
            __syncthreads();
            p ^= 1;
        }
    }

    // epilogue
    float4 bia0 = *reinterpret_cast<const float4*>(bias + bn + tx * 8);
    float4 bia1 = *reinterpret_cast<const float4*>(bias + bn + tx * 8 + 4);
#pragma unroll
    for (int i = 0; i < 8; i++) {
        float* crow = C + (size_t)(bm + ty * 8 + i) * N + bn + tx * 8;
        float v[8];
        unpack2(acc2[i][0], v[0], v[1]);
        unpack2(acc2[i][1], v[2], v[3]);
        unpack2(acc2[i][2], v[4], v[5]);
        unpack2(acc2[i][3], v[6], v[7]);
        float4 r0, r1;
        r0.x = v[0] + bia0.x; r0.y = v[1] + bia0.y;
        r0.z = v[2] + bia0.z; r0.w = v[3] + bia0.w;
        r1.x = v[4] + bia1.x; r1.y = v[5] + bia1.y;
        r1.z = v[6] + bia1.z; r1.w = v[7] + bia1.w;
        if (ADD_C) {
            float4 c0 = *reinterpret_cast<const float4*>(crow);
            float4 c1 = *reinterpret_cast<const float4*>(crow + 4);
            r0.x += c0.x; r0.y += c0.y; r0.z += c0.z; r0.w += c0.w;
            r1.x += c1.x; r1.y += c1.y; r1.z += c1.z; r1.w += c1.w;
        }
        *reinterpret_cast<float4*>(crow)     = r0;
        *reinterpret_cast<float4*>(crow + 4) = r1;
    }
}

// ---------------- fused tail: ll, mean, sampling ----------------
__global__ void fused_tail(const float* __restrict__ x, const float* __restrict__ mask,
                           float* __restrict__ out,
                           uint32_t kc0, uint32_t kc1, uint32_t kn0, uint32_t kn1)
{
    int t = blockIdx.x * blockDim.x + threadIdx.x;
    if (t >= BB * DD) return;
    int b = t >> 8;
    int d = t & (DD - 1);

    const float* row = g_OUT30 + (size_t)b * NOUT + d * 30;
    float lg[KK], mu[KK], sc[KK];
#pragma unroll
    for (int j = 0; j < KK; j++) lg[j] = row[j];
#pragma unroll
    for (int j = 0; j < KK; j++) mu[j] = row[KK + j];
#pragma unroll
    for (int j = 0; j < KK; j++) {
        float v = row[2 * KK + j];
        sc[j] = fmaxf(v, 0.0f) + log1pf(expf(-fabsf(v))) + 0.001f;
    }
    float q  = 1.0f - mask[t];
    float xu = x[t] * q;

    float mx = lg[0];
#pragma unroll
    for (int j = 1; j < KK; j++) mx = fmaxf(mx, lg[j]);
    float se = 0.0f;
#pragma unroll
    for (int j = 0; j < KK; j++) se += expf(lg[j] - mx);
    float lse = logf(se);

    float term[KK];
    float m2 = -1e30f;
#pragma unroll
    for (int j = 0; j < KK; j++) {
        float z   = (xu - mu[j]) / sc[j];
        float cll = -0.5f * z * z - logf(sc[j]) - 0.9189385332046727f;
        term[j] = (lg[j] - mx - lse) + cll;
        m2 = fmaxf(m2, term[j]);
    }
    float s2 = 0.0f;
#pragma unroll
    for (int j = 0; j < KK; j++) s2 += expf(term[j] - m2);
    out[t] = (m2 + logf(s2)) * q;

    float pm = 0.0f;
#pragma unroll
    for (int j = 0; j < KK; j++) pm += (expf(lg[j] - mx) / se) * mu[j];
    out[BB * DD + SS * BB * DD + t] = pm * q;

    float* smp = out + BB * DD;

#pragma unroll 1
    for (int s = 0; s < SS; s++) {
        uint32_t idx_e = (uint32_t)(s * BB + b) * DD + (uint32_t)d;  // (S,B,D) flat
        uint32_t base  = idx_e * KK;                                  // (S,B,D,K) flat
        float best = -1e30f;
        int a = 0;
#pragma unroll
        for (int j = 0; j < KK; j++) {
            uint32_t bits = tf_bits(kc0, kc1, base + j);
            float v = lg[j] + gumbel_from_bits(bits);
            if (v > best) { best = v; a = j; }
        }
        float mua = 0.f, sca = 0.f;
#pragma unroll
        for (int j = 0; j < KK; j++) {
            if (a == j) { mua = mu[j]; sca = sc[j]; }
        }
        uint32_t ebits = tf_bits(kn0, kn1, idx_e);
        const float LO = -0.99999994f;
        float u = fmaxf(LO, fmaf(bits_to_unit(ebits), 2.0f, LO));
        float eps = 1.41421356237309515f * erfinv_xla(u);
        smp[(b * SS + s) * DD + d] = (mua + sca * eps) * q;
    }
}

// ---------------- launch ----------------
extern "C" void kernel_launch(void* const* d_in, const int* in_sizes, int n_in,
                              void* d_out, int out_size)
{
    const float* x     = (const float*)d_in[0];
    const float* mask  = (const float*)d_in[1];
    const float* W_in  = (const float*)d_in[2];
    const float* b_in  = (const float*)d_in[3];
    const float* W1    = (const float*)d_in[4];
    const float* b1    = (const float*)d_in[5];
    const float* W2    = (const float*)d_in[6];
    const float* b2    = (const float*)d_in[7];
    const float* W_fin = (const float*)d_in[8];
    const float* b_fin = (const float*)d_in[9];
    float* out = (float*)d_out;

    float *dA0, *dH, *dT, *dWFP, *dBFP, *dOUT30;
    cudaGetSymbolAddress((void**)&dA0,    g_A0);
    cudaGetSymbolAddress((void**)&dH,     g_H);
    cudaGetSymbolAddress((void**)&dT,     g_T);
    cudaGetSymbolAddress((void**)&dWFP,   g_WFP);
    cudaGetSymbolAddress((void**)&dBFP,   g_BFP);
    cudaGetSymbolAddress((void**)&dOUT30, g_OUT30);

    // JAX partitionable (fold-like) split of key(1234)
    uint32_t kc0, kc1, kn0, kn1;
    threefry2x32(0u, 1234u, 0u, 0u, kc0, kc1);   // keys[0] -> categorical
    threefry2x32(0u, 1234u, 0u, 1u, kn0, kn1);   // keys[1] -> normal

    prep_kernel<<<(BB * 2 * DD + 255) / 256, 256>>>(x, mask);
    gather_kernel<<<(HH * NOUT + NOUT + 255) / 256, 256>>>(W_fin, b_fin);

    // layer GEMMs: 64x128 tiles -> grid 4 x 64 = 256 CTAs
    dim3 g1(HH / 128, BB / 64);
    sgemm_f32x2<128, false, false><<<g1, 128>>>(dA0, W_in, b_in, dH, BB, HH, 2 * DD);
    for (int l = 0; l < LL; l++) {
        sgemm_f32x2<128, true, false><<<g1, 128>>>(dH, W1 + (size_t)l * HH * HH, b1 + l * HH, dT, BB, HH, HH);
        sgemm_f32x2<128, true, true><<<g1, 128>>>(dT, W2 + (size_t)l * HH * HH, b2 + l * HH, dH, BB, HH, HH);
    }
    // final pruned GEMM: 128x128 tiles -> grid 60 x 32 = 1920 CTAs
    dim3 g2(NOUT / 128, BB / 128);
    sgemm_f32x2<256, false, false><<<g2, 256>>>(dH, dWFP, dBFP, dOUT30, BB, NOUT, HH);

    fused_tail<<<(BB * DD + 255) / 256, 256>>>(x, mask, out, kc0, kc1, kn0, kn1);
}

// round 4
// speedup vs baseline: 1.1668x; 1.0120x over previous
#include <cuda_runtime.h>
#include <cstdint>
#include <math.h>

// ---------------- problem constants ----------------
#define BB   4096
#define DD   256
#define HH   512
#define KK   10
#define HEADN 94
#define LL   4
#define SS   10
#define NOUT (DD * 30)          // 7680 pruned output cols (logits/means/scales)

typedef unsigned long long ull;

// ---------------- scratch (device globals; no allocation allowed) ----------------
__device__ float g_H[BB * HH];               // running hidden state
__device__ float g_T[BB * HH];               // temp
__device__ float g_WFP[HH * NOUT];           // gathered W_fin (512 x 7680)
__device__ float g_BFP[NOUT];                // gathered b_fin
__device__ float g_OUT30[(size_t)BB * NOUT]; // final params (4096 x 7680)

// ---------------- f32x2 helpers ----------------
__device__ __forceinline__ ull pack2(float lo, float hi) {
    ull r; asm("mov.b64 %0, {%1, %2};" : "=l"(r) : "f"(lo), "f"(hi)); return r;
}
__device__ __forceinline__ ull fma2(ull a, ull b, ull c) {
    ull r; asm("fma.rn.f32x2 %0, %1, %2, %3;" : "=l"(r) : "l"(a), "l"(b), "l"(c)); return r;
}
__device__ __forceinline__ void unpack2(ull v, float& lo, float& hi) {
    asm("mov.b64 {%0, %1}, %2;" : "=f"(lo), "=f"(hi) : "l"(v));
}

// ---------------- threefry2x32 (bit-exact JAX) ----------------
__host__ __device__ __forceinline__ uint32_t rotl32(uint32_t x, int r) {
#if defined(__CUDA_ARCH__)
    return __funnelshift_l(x, x, r);
#else
    return (x << r) | (x >> (32 - r));
#endif
}

__host__ __device__ __forceinline__ void threefry2x32(
    uint32_t k0, uint32_t k1, uint32_t x0, uint32_t x1,
    uint32_t& o0, uint32_t& o1)
{
    uint32_t k2 = k0 ^ k1 ^ 0x1BD11BDAu;
    x0 += k0; x1 += k1;
    x0 += x1; x1 = rotl32(x1, 13); x1 ^= x0;
    x0 += x1; x1 = rotl32(x1, 15); x1 ^= x0;
    x0 += x1; x1 = rotl32(x1, 26); x1 ^= x0;
    x0 += x1; x1 = rotl32(x1, 6);  x1 ^= x0;
    x0 += k1; x1 += k2 + 1u;
    x0 += x1; x1 = rotl32(x1, 17); x1 ^= x0;
    x0 += x1; x1 = rotl32(x1, 29); x1 ^= x0;
    x0 += x1; x1 = rotl32(x1, 16); x1 ^= x0;
    x0 += x1; x1 = rotl32(x1, 24); x1 ^= x0;
    x0 += k2; x1 += k0 + 2u;
    x0 += x1; x1 = rotl32(x1, 13); x1 ^= x0;
    x0 += x1; x1 = rotl32(x1, 15); x1 ^= x0;
    x0 += x1; x1 = rotl32(x1, 26); x1 ^= x0;
    x0 += x1; x1 = rotl32(x1, 6);  x1 ^= x0;
    x0 += k0; x1 += k1 + 3u;
    x0 += x1; x1 = rotl32(x1, 17); x1 ^= x0;
    x0 += x1; x1 = rotl32(x1, 29); x1 ^= x0;
    x0 += x1; x1 = rotl32(x1, 16); x1 ^= x0;
    x0 += x1; x1 = rotl32(x1, 24); x1 ^= x0;
    x0 += k1; x1 += k2 + 4u;
    x0 += x1; x1 = rotl32(x1, 13); x1 ^= x0;
    x0 += x1; x1 = rotl32(x1, 15); x1 ^= x0;
    x0 += x1; x1 = rotl32(x1, 26); x1 ^= x0;
    x0 += x1; x1 = rotl32(x1, 6);  x1 ^= x0;
    x0 += k2; x1 += k0 + 5u;
    o0 = x0; o1 = x1;
}

__device__ __forceinline__ uint32_t tf_bits(uint32_t k0, uint32_t k1, uint32_t idx) {
    uint32_t o0, o1;
    threefry2x32(k0, k1, 0u, idx, o0, o1);
    return o0 ^ o1;
}

// ---------------- XLA-exact erfinv (Giles, f32 path) ----------------
__device__ __forceinline__ float erfinv_xla(float x) {
    float w = -logf((1.0f - x) * (1.0f + x));
    float p;
    if (w < 5.0f) {
        w -= 2.5f;
        p = 2.81022636e-08f;
        p = fmaf(p, w, 3.43273939e-07f);
        p = fmaf(p, w, -3.5233877e-06f);
        p = fmaf(p, w, -4.39150654e-06f);
        p = fmaf(p, w, 0.00021858087f);
        p = fmaf(p, w, -0.00125372503f);
        p = fmaf(p, w, -0.00417768164f);
        p = fmaf(p, w, 0.246640727f);
        p = fmaf(p, w, 1.50140941f);
    } else {
        w = sqrtf(w) - 3.0f;
        p = -0.000200214257f;
        p = fmaf(p, w, 0.000100950558f);
        p = fmaf(p, w, 0.00134934322f);
        p = fmaf(p, w, -0.00367342844f);
        p = fmaf(p, w, 0.00573950773f);
        p = fmaf(p, w, -0.0076224613f);
        p = fmaf(p, w, 0.00943887047f);
        p = fmaf(p, w, 1.00167406f);
        p = fmaf(p, w, 2.83297682f);
    }
    return p * x;
}

__device__ __forceinline__ float bits_to_unit(uint32_t b) {
    return __uint_as_float((b >> 9) | 0x3F800000u) - 1.0f;
}

__device__ __forceinline__ float gumbel_from_bits(uint32_t bits) {
    const float TINY = 1.17549435e-38f;
    float f = bits_to_unit(bits);
    float u = fmaxf(TINY, f + TINY);
    return -logf(-logf(u));
}

// ---------------- gather kernel ----------------
__global__ void gather_kernel(const float* __restrict__ Wf, const float* __restrict__ bf) {
    int t = blockIdx.x * blockDim.x + threadIdx.x;
    const int total = HH * NOUT;
    if (t < total) {
        int c = t % NOUT;
        int h = t / NOUT;
        int d = c / 30, j = c - d * 30;
        g_WFP[t] = Wf[(size_t)h * (DD * HEADN) + d * HEADN + j];
    } else if (t < total + NOUT) {
        int c = t - total;
        int d = c / 30, j = c - d * 30;
        g_BFP[c] = bf[d * HEADN + j];
    }
}

// ---------------- fp32 SGEMM, f32x2 inner ----------------
// Tile 64x128, BK=16, 128 threads, 8x8 microtile, double-buffered smem, occ 3.
// PREP: A is concat(x*mask, mask) computed on the fly (Kd must be 512).
template <bool RELU_A, bool ADD_C, bool PREP>
__global__ __launch_bounds__(128, 3) void sgemm_f32x2(
    const float* __restrict__ A, const float* __restrict__ Xm,
    const float* __restrict__ Bm,
    const float* __restrict__ bias, float* __restrict__ C,
    int N, int Kd)
{
    __shared__ float As[2][16][68];   // transposed A tile, padded
    __shared__ float Bs[2][16][128];

    const int t  = threadIdx.x;
    const int bm = blockIdx.y * 64;
    const int bn = blockIdx.x * 128;
    const int tx = t & 15;
    const int ty = t >> 4;           // 0..7

    // A fragment: row = t>>1, two float4 at k offsets (t&1)*8 + {0,4}
    const int arow = t >> 1;         // 0..63
    const int ak   = (t & 1) * 8;
    // B fragment: 4 float4: row = (t>>5) + 4*i, col = (t&31)*4
    const int brow = t >> 5;         // 0..3
    const int bcol = (t & 31) * 4;

    ull acc2[8][4];
#pragma unroll
    for (int i = 0; i < 8; i++)
#pragma unroll
        for (int j = 0; j < 4; j++) acc2[i][j] = 0ull;

    float4 aR0, aR1, bR[4];

    auto loadG = [&](int k0) {
        if (PREP) {
            // A row 'bm+arow', cols k0+ak .. k0+ak+7 of [x*mask | mask]
            int col0 = k0 + ak;
            const float* xrow = A  + (size_t)(bm + arow) * DD;   // A = x
            const float* mrow = Xm + (size_t)(bm + arow) * DD;   // Xm = mask
            if (col0 < DD) {
                float4 xv = *reinterpret_cast<const float4*>(xrow + col0);
                float4 mv = *reinterpret_cast<const float4*>(mrow + col0);
                aR0 = make_float4(xv.x * mv.x, xv.y * mv.y, xv.z * mv.z, xv.w * mv.w);
                xv = *reinterpret_cast<const float4*>(xrow + col0 + 4);
                mv = *reinterpret_cast<const float4*>(mrow + col0 + 4);
                aR1 = make_float4(xv.x * mv.x, xv.y * mv.y, xv.z * mv.z, xv.w * mv.w);
            } else {
                aR0 = *reinterpret_cast<const float4*>(mrow + col0 - DD);
                aR1 = *reinterpret_cast<const float4*>(mrow + col0 - DD + 4);
            }
        } else {
            const float* Ap = A + (size_t)(bm + arow) * Kd + k0 + ak;
            aR0 = *reinterpret_cast<const float4*>(Ap);
            aR1 = *reinterpret_cast<const float4*>(Ap + 4);
            if (RELU_A) {
                aR0.x = fmaxf(aR0.x, 0.f); aR0.y = fmaxf(aR0.y, 0.f);
                aR0.z = fmaxf(aR0.z, 0.f); aR0.w = fmaxf(aR0.w, 0.f);
                aR1.x = fmaxf(aR1.x, 0.f); aR1.y = fmaxf(aR1.y, 0.f);
                aR1.z = fmaxf(aR1.z, 0.f); aR1.w = fmaxf(aR1.w, 0.f);
            }
        }
#pragma unroll
        for (int i = 0; i < 4; i++)
            bR[i] = *reinterpret_cast<const float4*>(Bm + (size_t)(k0 + brow + 4 * i) * N + bn + bcol);
    };
    auto storeS = [&](int p) {
        As[p][ak + 0][arow] = aR0.x;
        As[p][ak + 1][arow] = aR0.y;
        As[p][ak + 2][arow] = aR0.z;
        As[p][ak + 3][arow] = aR0.w;
        As[p][ak + 4][arow] = aR1.x;
        As[p][ak + 5][arow] = aR1.y;
        As[p][ak + 6][arow] = aR1.z;
        As[p][ak + 7][arow] = aR1.w;
#pragma unroll
        for (int i = 0; i < 4; i++)
            *reinterpret_cast<float4*>(&Bs[p][brow + 4 * i][bcol]) = bR[i];
    };

    loadG(0);
    storeS(0);
    __syncthreads();

    const int T = Kd >> 4;
    int p = 0;
#pragma unroll 1
    for (int tk = 0; tk < T; tk++) {
        if (tk + 1 < T) loadG((tk + 1) << 4);
#pragma unroll
        for (int kk = 0; kk < 16; kk++) {
            float a[8];
            *reinterpret_cast<float4*>(a)     = *reinterpret_cast<const float4*>(&As[p][kk][ty * 8]);
            *reinterpret_cast<float4*>(a + 4) = *reinterpret_cast<const float4*>(&As[p][kk][ty * 8 + 4]);
            ulonglong2 bq0 = *reinterpret_cast<const ulonglong2*>(&Bs[p][kk][tx * 8]);
            ulonglong2 bq1 = *reinterpret_cast<const ulonglong2*>(&Bs[p][kk][tx * 8 + 4]);
#pragma unroll
            for (int i = 0; i < 8; i++) {
                ull a2 = pack2(a[i], a[i]);
                acc2[i][0] = fma2(a2, bq0.x, acc2[i][0]);
                acc2[i][1] = fma2(a2, bq0.y, acc2[i][1]);
                acc2[i][2] = fma2(a2, bq1.x, acc2[i][2]);
                acc2[i][3] = fma2(a2, bq1.y, acc2[i][3]);
            }
        }
        if (tk + 1 < T) {
            storeS(p ^ 1);
            __syncthreads();
            p ^= 1;
        }
    }

    // epilogue
    float4 bia0 = *reinterpret_cast<const float4*>(bias + bn + tx * 8);
    float4 bia1 = *reinterpret_cast<const float4*>(bias + bn + tx * 8 + 4);
#pragma unroll
    for (int i = 0; i < 8; i++) {
        float* crow = C + (size_t)(bm + ty * 8 + i) * N + bn + tx * 8;
        float v[8];
        unpack2(acc2[i][0], v[0], v[1]);
        unpack2(acc2[i][1], v[2], v[3]);
        unpack2(acc2[i][2], v[4], v[5]);
        unpack2(acc2[i][3], v[6], v[7]);
        float4 r0, r1;
        r0.x = v[0] + bia0.x; r0.y = v[1] + bia0.y;
        r0.z = v[2] + bia0.z; r0.w = v[3] + bia0.w;
        r1.x = v[4] + bia1.x; r1.y = v[5] + bia1.y;
        r1.z = v[6] + bia1.z; r1.w = v[7] + bia1.w;
        if (ADD_C) {
            float4 c0 = *reinterpret_cast<const float4*>(crow);
            float4 c1 = *reinterpret_cast<const float4*>(crow + 4);
            r0.x += c0.x; r0.y += c0.y; r0.z += c0.z; r0.w += c0.w;
            r1.x += c1.x; r1.y += c1.y; r1.z += c1.z; r1.w += c1.w;
        }
        *reinterpret_cast<float4*>(crow)     = r0;
        *reinterpret_cast<float4*>(crow + 4) = r1;
    }
}

// ---------------- fused tail: ll, mean, sampling ----------------
__global__ void fused_tail(const float* __restrict__ x, const float* __restrict__ mask,
                           float* __restrict__ out,
                           uint32_t kc0, uint32_t kc1, uint32_t kn0, uint32_t kn1)
{
    int t = blockIdx.x * blockDim.x + threadIdx.x;
    if (t >= BB * DD) return;
    int b = t >> 8;
    int d = t & (DD - 1);

    const float* row = g_OUT30 + (size_t)b * NOUT + d * 30;
    float lg[KK], mu[KK], sc[KK];
#pragma unroll
    for (int j = 0; j < KK; j++) lg[j] = row[j];
#pragma unroll
    for (int j = 0; j < KK; j++) mu[j] = row[KK + j];
#pragma unroll
    for (int j = 0; j < KK; j++) {
        float v = row[2 * KK + j];
        sc[j] = fmaxf(v, 0.0f) + log1pf(expf(-fabsf(v))) + 0.001f;
    }
    float q  = 1.0f - mask[t];
    float xu = x[t] * q;

    float mx = lg[0];
#pragma unroll
    for (int j = 1; j < KK; j++) mx = fmaxf(mx, lg[j]);
    float se = 0.0f;
#pragma unroll
    for (int j = 0; j < KK; j++) se += expf(lg[j] - mx);
    float lse = logf(se);

    float term[KK];
    float m2 = -1e30f;
#pragma unroll
    for (int j = 0; j < KK; j++) {
        float z   = (xu - mu[j]) / sc[j];
        float cll = -0.5f * z * z - logf(sc[j]) - 0.9189385332046727f;
        term[j] = (lg[j] - mx - lse) + cll;
        m2 = fmaxf(m2, term[j]);
    }
    float s2 = 0.0f;
#pragma unroll
    for (int j = 0; j < KK; j++) s2 += expf(term[j] - m2);
    out[t] = (m2 + logf(s2)) * q;

    float pm = 0.0f;
#pragma unroll
    for (int j = 0; j < KK; j++) pm += (expf(lg[j] - mx) / se) * mu[j];
    out[BB * DD + SS * BB * DD + t] = pm * q;

    float* smp = out + BB * DD;

#pragma unroll 1
    for (int s = 0; s < SS; s++) {
        uint32_t idx_e = (uint32_t)(s * BB + b) * DD + (uint32_t)d;  // (S,B,D) flat
        uint32_t base  = idx_e * KK;                                  // (S,B,D,K) flat
        float best = -1e30f;
        int a = 0;
#pragma unroll
        for (int j = 0; j < KK; j++) {
            uint32_t bits = tf_bits(kc0, kc1, base + j);
            float v = lg[j] + gumbel_from_bits(bits);
            if (v > best) { best = v; a = j; }
        }
        float mua = 0.f, sca = 0.f;
#pragma unroll
        for (int j = 0; j < KK; j++) {
            if (a == j) { mua = mu[j]; sca = sc[j]; }
        }
        uint32_t ebits = tf_bits(kn0, kn1, idx_e);
        const float LO = -0.99999994f;
        float u = fmaxf(LO, fmaf(bits_to_unit(ebits), 2.0f, LO));
        float eps = 1.41421356237309515f * erfinv_xla(u);
        smp[(b * SS + s) * DD + d] = (mua + sca * eps) * q;
    }
}

// ---------------- launch ----------------
extern "C" void kernel_launch(void* const* d_in, const int* in_sizes, int n_in,
                              void* d_out, int out_size)
{
    const float* x     = (const float*)d_in[0];
    const float* mask  = (const float*)d_in[1];
    const float* W_in  = (const float*)d_in[2];
    const float* b_in  = (const float*)d_in[3];
    const float* W1    = (const float*)d_in[4];
    const float* b1    = (const float*)d_in[5];
    const float* W2    = (const float*)d_in[6];
    const float* b2    = (const float*)d_in[7];
    const float* W_fin = (const float*)d_in[8];
    const float* b_fin = (const float*)d_in[9];
    float* out = (float*)d_out;

    float *dH, *dT, *dWFP, *dBFP, *dOUT30;
    cudaGetSymbolAddress((void**)&dH,     g_H);
    cudaGetSymbolAddress((void**)&dT,     g_T);
    cudaGetSymbolAddress((void**)&dWFP,   g_WFP);
    cudaGetSymbolAddress((void**)&dBFP,   g_BFP);
    cudaGetSymbolAddress((void**)&dOUT30, g_OUT30);

    // JAX partitionable (fold-like) split of key(1234)
    uint32_t kc0, kc1, kn0, kn1;
    threefry2x32(0u, 1234u, 0u, 0u, kc0, kc1);   // keys[0] -> categorical
    threefry2x32(0u, 1234u, 0u, 1u, kn0, kn1);   // keys[1] -> normal

    gather_kernel<<<(HH * NOUT + NOUT + 255) / 256, 256>>>(W_fin, b_fin);

    dim3 blk(128);
    dim3 g1(HH / 128, BB / 64);                  // 4 x 64 = 256 CTAs
    // h = concat(x*mask, mask) @ W_in + b_in   (prep fused into A path)
    sgemm_f32x2<false, false, true><<<g1, blk>>>(x, mask, W_in, b_in, dH, HH, 2 * DD);
    for (int l = 0; l < LL; l++) {
        sgemm_f32x2<true, false, false><<<g1, blk>>>(dH, nullptr, W1 + (size_t)l * HH * HH, b1 + l * HH, dT, HH, HH);
        sgemm_f32x2<true, true,  false><<<g1, blk>>>(dT, nullptr, W2 + (size_t)l * HH * HH, b2 + l * HH, dH, HH, HH);
    }
    // final pruned GEMM: 64x128 tiles -> grid 60 x 64 = 3840 CTAs
    dim3 g2(NOUT / 128, BB / 64);
    sgemm_f32x2<false, false, false><<<g2, blk>>>(dH, nullptr, dWFP, dBFP, dOUT30, NOUT, HH);

    fused_tail<<<(BB * DD + 255) / 256, 256>>>(x, mask, out, kc0, kc1, kn0, kn1);
}